// round 1
// baseline (speedup 1.0000x reference)
#include <cuda_runtime.h>

#define Bn   32
#define Cn   512
#define HWn  448
#define NHn  8
#define DKn  64
#define NKVn 1024
#define NQn  (HWn * NHn * DKn)   // 229376
#define BHT  (Bn * NHn)          // 256
#define SCALE 0.125f

// ---------------- scratch (device globals; no allocation allowed) ----------
__device__ float g_kv [(size_t)Bn * HWn * NKVn];        //  14.7M  kv[b][j][h*128 + t] (t<64: k, t>=64: v)
__device__ float g_q  [(size_t)Bn * NQn];               //   7.3M  q[b][i*512 + h*64 + d]
__device__ float g_E  [(size_t)BHT * HWn * HWn];        //  51.4M  E[bh][i][j] = exp(scale*q.k)
__device__ float g_cs [BHT * HWn];                      //         colsum over i per (bh, j)
__device__ float g_vn [(size_t)BHT * HWn * DKn];        //   7.3M  v'[bh][j][d] = v / colsum
__device__ float g_res[(size_t)Bn * HWn * Cn];          //   7.3M  attn output [b][i][h*64+d]

// ---------------- KV projection: per b, [448,512] @ [512,1024] -------------
// A[j,c] = x[b,c,j] (transposed read), B = W_kv. 64x64 tiles, BK=16.
__global__ __launch_bounds__(256) void k_kv(const float* __restrict__ x,
                                            const float* __restrict__ Wkv,
                                            const float* __restrict__ bkv) {
    int b = blockIdx.z, j0 = blockIdx.y * 64, n0 = blockIdx.x * 64;
    __shared__ float As[16][64];   // [kk(c)][jj]
    __shared__ float Bs[16][64];   // [kk][nn]
    int tid = threadIdx.x;
    int tx = tid & 15, ty = tid >> 4;
    float acc[4][4] = {};
    const float* xb = x + (size_t)b * Cn * HWn;
    for (int k0 = 0; k0 < Cn; k0 += 16) {
        {
            int jj = tid & 63, c4 = tid >> 6;
            #pragma unroll
            for (int p = 0; p < 4; p++) {
                int cc = p * 4 + c4;
                As[cc][jj] = xb[(size_t)(k0 + cc) * HWn + j0 + jj];
            }
        }
        {
            int nn = tid & 63, c4 = tid >> 6;
            #pragma unroll
            for (int p = 0; p < 4; p++) {
                int cc = p * 4 + c4;
                Bs[cc][nn] = Wkv[(size_t)(k0 + cc) * NKVn + n0 + nn];
            }
        }
        __syncthreads();
        #pragma unroll
        for (int kk = 0; kk < 16; kk++) {
            float4 a = *reinterpret_cast<float4*>(&As[kk][ty * 4]);
            float4 bb = *reinterpret_cast<float4*>(&Bs[kk][tx * 4]);
            float av[4] = {a.x, a.y, a.z, a.w};
            float bv[4] = {bb.x, bb.y, bb.z, bb.w};
            #pragma unroll
            for (int i = 0; i < 4; i++)
                #pragma unroll
                for (int j = 0; j < 4; j++) acc[i][j] += av[i] * bv[j];
        }
        __syncthreads();
    }
    #pragma unroll
    for (int i = 0; i < 4; i++) {
        int j = j0 + ty * 4 + i;
        float* op = g_kv + ((size_t)b * HWn + j) * NKVn + n0;
        #pragma unroll
        for (int q = 0; q < 4; q++) {
            int n = n0 + tx * 4 + q;
            op[tx * 4 + q] = acc[i][q] + bkv[n];
        }
    }
}

// ---------------- Q projection: [32,512] @ [512,229376] --------------------
// Tile: 32(M) x 128(N), BK=16. Thread micro 2x8.
__global__ __launch_bounds__(256) void k_q(const float* __restrict__ s,
                                           const float* __restrict__ Wq,
                                           const float* __restrict__ bq) {
    int n0 = blockIdx.x * 128;
    __shared__ float As[16][33];    // [kk][m], padded
    __shared__ float Bs[16][128];   // [kk][nn]
    int tid = threadIdx.x;
    int tx = tid & 15, ty = tid >> 4;   // m = ty*2+{0,1}, n = tx*8..
    float acc[2][8] = {};
    for (int k0 = 0; k0 < Cn; k0 += 16) {
        {
            int kk = tid & 15, m = tid >> 4;
            As[kk][m]      = s[(size_t)m * Cn + k0 + kk];
            As[kk][m + 16] = s[(size_t)(m + 16) * Cn + k0 + kk];
        }
        {
            int nn = tid & 127, k2 = tid >> 7;
            #pragma unroll
            for (int p = 0; p < 8; p++) {
                int kk = p * 2 + k2;
                Bs[kk][nn] = Wq[(size_t)(k0 + kk) * NQn + n0 + nn];
            }
        }
        __syncthreads();
        #pragma unroll
        for (int kk = 0; kk < 16; kk++) {
            float a0 = As[kk][ty * 2], a1 = As[kk][ty * 2 + 1];
            float4 b0 = *reinterpret_cast<float4*>(&Bs[kk][tx * 8]);
            float4 b1 = *reinterpret_cast<float4*>(&Bs[kk][tx * 8 + 4]);
            float bv[8] = {b0.x, b0.y, b0.z, b0.w, b1.x, b1.y, b1.z, b1.w};
            #pragma unroll
            for (int i = 0; i < 8; i++) { acc[0][i] += a0 * bv[i]; acc[1][i] += a1 * bv[i]; }
        }
        __syncthreads();
    }
    #pragma unroll
    for (int mm = 0; mm < 2; mm++) {
        int m = ty * 2 + mm;
        #pragma unroll
        for (int i = 0; i < 8; i++) {
            int n = n0 + tx * 8 + i;
            g_q[(size_t)m * NQn + n] = acc[mm][i] + bq[n];
        }
    }
}

// ---------------- zero colsum ----------------------------------------------
__global__ void k_zero() {
    int i = blockIdx.x * blockDim.x + threadIdx.x;
    if (i < BHT * HWn) g_cs[i] = 0.0f;
}

// ---------------- logits -> E = exp(scale*q.k), accumulate column sums -----
// Per (bh): Q[448,64] x K[448,64]^T. 64x64 output tiles, full K-dim (64).
__global__ __launch_bounds__(256) void k_attE() {
    int bh = blockIdx.z; int b = bh >> 3, h = bh & 7;
    int i0 = blockIdx.y * 64, j0 = blockIdx.x * 64;
    __shared__ float Qs[64][65];   // [d][i]
    __shared__ float Ks[64][65];   // [d][j]
    int tid = threadIdx.x;
    int tx = tid & 15, ty = tid >> 4;
    {
        int d = tid & 63, i4 = tid >> 6;
        #pragma unroll
        for (int p = 0; p < 16; p++) {
            int ii = p * 4 + i4;
            Qs[d][ii] = g_q[(size_t)b * NQn + (size_t)(i0 + ii) * 512 + h * 64 + d];
            Ks[d][ii] = g_kv[((size_t)b * HWn + (j0 + ii)) * NKVn + h * 128 + d];
        }
    }
    __syncthreads();
    float acc[4][4] = {};
    #pragma unroll 8
    for (int kk = 0; kk < 64; kk++) {
        float av[4], bv[4];
        #pragma unroll
        for (int i = 0; i < 4; i++) av[i] = Qs[kk][ty * 4 + i];
        #pragma unroll
        for (int i = 0; i < 4; i++) bv[i] = Ks[kk][tx * 4 + i];
        #pragma unroll
        for (int i = 0; i < 4; i++)
            #pragma unroll
            for (int j = 0; j < 4; j++) acc[i][j] += av[i] * bv[j];
    }
    // write E, track per-thread column partial sums
    float cs[4] = {};
    #pragma unroll
    for (int i = 0; i < 4; i++) {
        int ig = i0 + ty * 4 + i;
        float* Ep = g_E + ((size_t)bh * HWn + ig) * HWn + j0;
        #pragma unroll
        for (int j = 0; j < 4; j++) {
            float e = __expf(acc[i][j] * SCALE);
            Ep[tx * 4 + j] = e;
            cs[j] += e;
        }
    }
    __syncthreads();
    #pragma unroll
    for (int j = 0; j < 4; j++) Qs[ty][tx * 4 + j] = cs[j];
    __syncthreads();
    if (tid < 64) {
        float ssum = 0.0f;
        #pragma unroll
        for (int t = 0; t < 16; t++) ssum += Qs[t][tid];
        atomicAdd(&g_cs[bh * HWn + j0 + tid], ssum);
    }
}

// ---------------- fold 1/colsum into V -------------------------------------
__global__ void k_vnorm() {
    int idx = blockIdx.x * blockDim.x + threadIdx.x;
    if (idx >= BHT * HWn * DKn) return;
    int d = idx & 63;
    int j = (idx >> 6) % HWn;
    int bh = idx / (HWn * DKn);
    int b = bh >> 3, h = bh & 7;
    float v = g_kv[((size_t)b * HWn + j) * NKVn + h * 128 + 64 + d];
    g_vn[idx] = v / g_cs[bh * HWn + j];
}

// ---------------- AV: per (bh), [448,448] @ [448,64] -----------------------
__global__ __launch_bounds__(256) void k_av() {
    int bh = blockIdx.z; int b = bh >> 3, h = bh & 7;
    int i0 = blockIdx.y * 64;
    __shared__ float As[16][65];   // [kk(j)][ii], padded
    __shared__ float Bs[16][64];   // [kk(j)][dd]
    int tid = threadIdx.x;
    int tx = tid & 15, ty = tid >> 4;
    float acc[4][4] = {};
    for (int k0 = 0; k0 < HWn; k0 += 16) {
        {
            int kk = tid & 15, i4 = tid >> 4;
            #pragma unroll
            for (int p = 0; p < 4; p++) {
                int ii = p * 16 + i4;
                As[kk][ii] = g_E[((size_t)bh * HWn + i0 + ii) * HWn + k0 + kk];
            }
        }
        {
            int dd = tid & 63, k4 = tid >> 6;
            #pragma unroll
            for (int p = 0; p < 4; p++) {
                int kk = p * 4 + k4;
                Bs[kk][dd] = g_vn[((size_t)bh * HWn + k0 + kk) * DKn + dd];
            }
        }
        __syncthreads();
        #pragma unroll
        for (int kk = 0; kk < 16; kk++) {
            float av[4];
            #pragma unroll
            for (int i = 0; i < 4; i++) av[i] = As[kk][ty * 4 + i];
            float4 bb = *reinterpret_cast<float4*>(&Bs[kk][tx * 4]);
            float bv[4] = {bb.x, bb.y, bb.z, bb.w};
            #pragma unroll
            for (int i = 0; i < 4; i++)
                #pragma unroll
                for (int j = 0; j < 4; j++) acc[i][j] += av[i] * bv[j];
        }
        __syncthreads();
    }
    #pragma unroll
    for (int i = 0; i < 4; i++) {
        int ig = i0 + ty * 4 + i;
        float* op = g_res + ((size_t)b * HWn + ig) * Cn + h * 64;
        #pragma unroll
        for (int j = 0; j < 4; j++) op[tx * 4 + j] = acc[i][j];
    }
}

// ---------------- O projection + bias + residual, transposed store ---------
// out[b,c,j] = sum_n g_res[b,j,n] * Wo[n,c] + bo[c] + x[b,c,j]
// Computed as C[c,j]: rows=c (As from Wo), cols=j (Bs from g_res) -> coalesced out.
__global__ __launch_bounds__(256) void k_out(const float* __restrict__ x,
                                             const float* __restrict__ Wo,
                                             const float* __restrict__ bo,
                                             float* __restrict__ out) {
    int b = blockIdx.z, c0 = blockIdx.y * 64, j0 = blockIdx.x * 64;
    __shared__ float As[16][64];   // [kk(n)][cc]
    __shared__ float Bs[16][65];   // [kk(n)][jj], padded
    int tid = threadIdx.x;
    int tx = tid & 15, ty = tid >> 4;
    float acc[4][4] = {};
    for (int k0 = 0; k0 < Cn; k0 += 16) {
        {
            int cc = tid & 63, k4 = tid >> 6;
            #pragma unroll
            for (int p = 0; p < 4; p++) {
                int kk = p * 4 + k4;
                As[kk][cc] = Wo[(size_t)(k0 + kk) * Cn + c0 + cc];
            }
        }
        {
            int kk = tid & 15, j4 = tid >> 4;
            #pragma unroll
            for (int p = 0; p < 4; p++) {
                int jj = p * 16 + j4;
                Bs[kk][jj] = g_res[((size_t)b * HWn + j0 + jj) * Cn + k0 + kk];
            }
        }
        __syncthreads();
        #pragma unroll
        for (int kk = 0; kk < 16; kk++) {
            float4 a = *reinterpret_cast<float4*>(&As[kk][ty * 4]);
            float av[4] = {a.x, a.y, a.z, a.w};
            float bv[4];
            #pragma unroll
            for (int i = 0; i < 4; i++) bv[i] = Bs[kk][tx * 4 + i];
            #pragma unroll
            for (int i = 0; i < 4; i++)
                #pragma unroll
                for (int j = 0; j < 4; j++) acc[i][j] += av[i] * bv[j];
        }
        __syncthreads();
    }
    #pragma unroll
    for (int i = 0; i < 4; i++) {
        int c = c0 + ty * 4 + i;
        size_t base = ((size_t)b * Cn + c) * HWn + j0;
        float bias = bo[c];
        #pragma unroll
        for (int j = 0; j < 4; j++) {
            size_t a = base + tx * 4 + j;
            out[a] = acc[i][j] + bias + x[a];
        }
    }
}

// ---------------- launch ----------------------------------------------------
extern "C" void kernel_launch(void* const* d_in, const int* in_sizes, int n_in,
                              void* d_out, int out_size) {
    // Match inputs by element count (all sizes distinct) for robustness.
    const float *x = 0, *s = 0, *Wkv = 0, *bkv = 0, *Wq = 0, *bq = 0, *Wo = 0, *bo = 0;
    for (int i = 0; i < n_in; i++) {
        const float* p = (const float*)d_in[i];
        switch (in_sizes[i]) {
            case 32 * 512 * 448: x = p; break;      // 7,340,032
            case 32 * 512:       s = p; break;      // 16,384
            case 512 * 1024:     Wkv = p; break;    // 524,288
            case 1024:           bkv = p; break;
            case 512 * 229376:   Wq = p; break;     // 117,440,512 (fits int? yes < 2^31)
            case 229376:         bq = p; break;
            case 512 * 512:      Wo = p; break;     // 262,144
            case 512:            bo = p; break;
        }
    }
    float* out = (float*)d_out;

    k_kv  <<<dim3(16, 7, Bn), 256>>>(x, Wkv, bkv);
    k_q   <<<NQn / 128, 256>>>(s, Wq, bq);
    k_zero<<<(BHT * HWn + 255) / 256, 256>>>();
    k_attE<<<dim3(7, 7, BHT), 256>>>();
    k_vnorm<<<(BHT * HWn * DKn + 255) / 256, 256>>>();
    k_av  <<<dim3(1, 7, BHT), 256>>>();
    k_out <<<dim3(7, 8, Bn), 256>>>(x, Wo, bo, out);
}

// round 2
// speedup vs baseline: 1.1191x; 1.1191x over previous
#include <cuda_runtime.h>

#define Bn   32
#define Cn   512
#define HWn  448
#define NHn  8
#define DKn  64
#define NKVn 1024
#define NQn  (HWn * NHn * DKn)   // 229376
#define BHT  (Bn * NHn)          // 256
#define SCALE 0.125f

typedef unsigned long long ull;

__device__ __forceinline__ ull pk2(float lo, float hi) {
    ull r; asm("mov.b64 %0, {%1,%2};" : "=l"(r) : "f"(lo), "f"(hi)); return r;
}
__device__ __forceinline__ void fma2(ull& d, ull a, ull b) {
    asm("fma.rn.f32x2 %0, %1, %2, %0;" : "+l"(d) : "l"(a), "l"(b));
}
__device__ __forceinline__ float2 up2(ull v) {
    float2 r; asm("mov.b64 {%0,%1}, %2;" : "=f"(r.x), "=f"(r.y) : "l"(v)); return r;
}

// ---------------- scratch (device globals; no allocation allowed) ----------
__device__ float g_kv [(size_t)Bn * HWn * NKVn];
__device__ float g_q  [(size_t)Bn * NQn];
__device__ float g_E  [(size_t)BHT * HWn * HWn];
__device__ float g_cs [BHT * HWn];
__device__ float g_vn [(size_t)BHT * HWn * DKn];
__device__ float g_res[(size_t)Bn * HWn * Cn];

// ================= KV projection: per b, [448,512]@[512,1024] ==============
// 128x128 tile, BK=16, micro 8x8, FFMA2 paired over n.
__global__ __launch_bounds__(256, 2) void k_kv(const float* __restrict__ x,
                                               const float* __restrict__ Wkv,
                                               const float* __restrict__ bkv) {
    int b = blockIdx.z, j0 = blockIdx.y * 128, n0 = blockIdx.x * 128;
    __shared__ float As[16][128];   // [c][j]
    __shared__ float Bs[16][128];   // [c][n]
    int tid = threadIdx.x, tx = tid & 15, ty = tid >> 4;
    ull acc[8][4] = {};
    const float* xb = x + (size_t)b * Cn * HWn;
    for (int k0 = 0; k0 < Cn; k0 += 16) {
        {
            int jj = tid & 127, c2 = tid >> 7;
            int j = min(j0 + jj, HWn - 1);
            #pragma unroll
            for (int p = 0; p < 8; p++) {
                int cc = p * 2 + c2;
                As[cc][jj] = xb[(size_t)(k0 + cc) * HWn + j];
            }
        }
        #pragma unroll
        for (int it = 0; it < 2; it++) {
            int f = it * 256 + tid;
            int row = f >> 5, c4 = f & 31;
            *(float4*)&Bs[row][c4 * 4] =
                *(const float4*)&Wkv[(size_t)(k0 + row) * NKVn + n0 + c4 * 4];
        }
        __syncthreads();
        #pragma unroll
        for (int kk = 0; kk < 16; kk++) {
            float4 a0 = *(float4*)&As[kk][ty * 8];
            float4 a1 = *(float4*)&As[kk][ty * 8 + 4];
            ull a2[8] = {pk2(a0.x,a0.x), pk2(a0.y,a0.y), pk2(a0.z,a0.z), pk2(a0.w,a0.w),
                         pk2(a1.x,a1.x), pk2(a1.y,a1.y), pk2(a1.z,a1.z), pk2(a1.w,a1.w)};
            const ull* bp = (const ull*)&Bs[kk][tx * 8];
            ull b2[4] = {bp[0], bp[1], bp[2], bp[3]};
            #pragma unroll
            for (int i = 0; i < 8; i++)
                #pragma unroll
                for (int j = 0; j < 4; j++) fma2(acc[i][j], a2[i], b2[j]);
        }
        __syncthreads();
    }
    float bn[8];
    #pragma unroll
    for (int q = 0; q < 8; q++) bn[q] = bkv[n0 + tx * 8 + q];
    #pragma unroll
    for (int i = 0; i < 8; i++) {
        int j = j0 + ty * 8 + i;
        if (j < HWn) {
            float* op = g_kv + ((size_t)b * HWn + j) * NKVn + n0 + tx * 8;
            float2 f0 = up2(acc[i][0]), f1 = up2(acc[i][1]);
            float2 f2 = up2(acc[i][2]), f3 = up2(acc[i][3]);
            *(float4*)op       = make_float4(f0.x+bn[0], f0.y+bn[1], f1.x+bn[2], f1.y+bn[3]);
            *(float4*)(op + 4) = make_float4(f2.x+bn[4], f2.y+bn[5], f3.x+bn[6], f3.y+bn[7]);
        }
    }
}

// ================= Q projection: [32,512]@[512,229376] =====================
// Tile 32x512, BK=16, micro 4x16 (ty=tid>>5 -> m, tx=tid&31 -> n).
__global__ __launch_bounds__(256, 2) void k_q(const float* __restrict__ s,
                                              const float* __restrict__ Wq,
                                              const float* __restrict__ bq) {
    int n0 = blockIdx.x * 512;
    __shared__ float As[16][33];
    __shared__ float Bs[16][512];
    int tid = threadIdx.x, tx = tid & 31, ty = tid >> 5;
    ull acc[4][8] = {};
    for (int k0 = 0; k0 < Cn; k0 += 16) {
        {
            int kk = tid & 15, m = tid >> 4;   // m 0..15
            As[kk][m]      = s[(size_t)m * Cn + k0 + kk];
            As[kk][m + 16] = s[(size_t)(m + 16) * Cn + k0 + kk];
        }
        #pragma unroll
        for (int it = 0; it < 8; it++) {
            int f = it * 256 + tid;
            int row = f >> 7, c4 = f & 127;
            *(float4*)&Bs[row][c4 * 4] =
                *(const float4*)&Wq[(size_t)(k0 + row) * NQn + n0 + c4 * 4];
        }
        __syncthreads();
        #pragma unroll
        for (int kk = 0; kk < 16; kk++) {
            ull a2[4];
            #pragma unroll
            for (int i = 0; i < 4; i++) { float a = As[kk][ty * 4 + i]; a2[i] = pk2(a, a); }
            const ull* bp = (const ull*)&Bs[kk][tx * 16];
            ull b2[8];
            #pragma unroll
            for (int j = 0; j < 8; j++) b2[j] = bp[j];
            #pragma unroll
            for (int i = 0; i < 4; i++)
                #pragma unroll
                for (int j = 0; j < 8; j++) fma2(acc[i][j], a2[i], b2[j]);
        }
        __syncthreads();
    }
    float bn[16];
    #pragma unroll
    for (int q = 0; q < 16; q++) bn[q] = bq[n0 + tx * 16 + q];
    #pragma unroll
    for (int i = 0; i < 4; i++) {
        int m = ty * 4 + i;
        float* op = g_q + (size_t)m * NQn + n0 + tx * 16;
        #pragma unroll
        for (int j2 = 0; j2 < 4; j2++) {
            float2 fa = up2(acc[i][j2 * 2]), fb = up2(acc[i][j2 * 2 + 1]);
            *(float4*)(op + j2 * 4) = make_float4(fa.x + bn[j2*4], fa.y + bn[j2*4+1],
                                                  fb.x + bn[j2*4+2], fb.y + bn[j2*4+3]);
        }
    }
}

// ================= zero colsum =============================================
__global__ void k_zero() {
    int i = blockIdx.x * blockDim.x + threadIdx.x;
    if (i < BHT * HWn) g_cs[i] = 0.0f;
}

// ================= E = exp(scale*q.k) + column sums ========================
// 128x128 tile per (bh, i-tile, j-tile). K=64, BK=32. micro 8x8.
__global__ __launch_bounds__(256, 2) void k_attE() {
    int bh = blockIdx.z, b = bh >> 3, h = bh & 7;
    int i0 = blockIdx.y * 128, j0 = blockIdx.x * 128;
    __shared__ float Qs[32][132];   // [d][i]
    __shared__ float Ks[32][132];   // [d][j]
    int tid = threadIdx.x, tx = tid & 15, ty = tid >> 4;
    ull acc[8][4] = {};
    for (int k0 = 0; k0 < DKn; k0 += 32) {
        #pragma unroll
        for (int it = 0; it < 4; it++) {
            int f = it * 256 + tid;           // 0..1023
            int ii = f >> 3, d4 = f & 7;
            int ic = min(i0 + ii, HWn - 1);
            int jc = min(j0 + ii, HWn - 1);
            float4 qv = *(const float4*)&g_q[(size_t)b * NQn + (size_t)ic * 512 + h * 64 + k0 + d4 * 4];
            float4 kv = *(const float4*)&g_kv[((size_t)b * HWn + jc) * NKVn + h * 128 + k0 + d4 * 4];
            Qs[d4*4+0][ii] = qv.x; Qs[d4*4+1][ii] = qv.y; Qs[d4*4+2][ii] = qv.z; Qs[d4*4+3][ii] = qv.w;
            Ks[d4*4+0][ii] = kv.x; Ks[d4*4+1][ii] = kv.y; Ks[d4*4+2][ii] = kv.z; Ks[d4*4+3][ii] = kv.w;
        }
        __syncthreads();
        #pragma unroll
        for (int kk = 0; kk < 32; kk++) {
            float4 a0 = *(float4*)&Qs[kk][ty * 8];
            float4 a1 = *(float4*)&Qs[kk][ty * 8 + 4];
            ull a2[8] = {pk2(a0.x,a0.x), pk2(a0.y,a0.y), pk2(a0.z,a0.z), pk2(a0.w,a0.w),
                         pk2(a1.x,a1.x), pk2(a1.y,a1.y), pk2(a1.z,a1.z), pk2(a1.w,a1.w)};
            const ull* bp = (const ull*)&Ks[kk][tx * 8];
            ull b2[4] = {bp[0], bp[1], bp[2], bp[3]};
            #pragma unroll
            for (int i = 0; i < 8; i++)
                #pragma unroll
                for (int j = 0; j < 4; j++) fma2(acc[i][j], a2[i], b2[j]);
        }
        __syncthreads();
    }
    // exp, store E, per-thread column sums
    int basej = j0 + tx * 8;
    float cs[8] = {};
    #pragma unroll
    for (int i = 0; i < 8; i++) {
        int ig = i0 + ty * 8 + i;
        float ev[8];
        #pragma unroll
        for (int j2 = 0; j2 < 4; j2++) {
            float2 f = up2(acc[i][j2]);
            ev[2*j2]   = __expf(f.x * SCALE);
            ev[2*j2+1] = __expf(f.y * SCALE);
        }
        if (ig < HWn) {
            float* Ep = g_E + ((size_t)bh * HWn + ig) * HWn + basej;
            if (basej + 7 < HWn) {
                *(float4*)Ep       = make_float4(ev[0], ev[1], ev[2], ev[3]);
                *(float4*)(Ep + 4) = make_float4(ev[4], ev[5], ev[6], ev[7]);
            } else {
                #pragma unroll
                for (int j = 0; j < 8; j++) if (basej + j < HWn) Ep[j] = ev[j];
            }
            #pragma unroll
            for (int j = 0; j < 8; j++) cs[j] += ev[j];
        }
    }
    __syncthreads();
    float (*red)[128] = (float(*)[128])Qs;
    #pragma unroll
    for (int j = 0; j < 8; j++) red[ty][tx * 8 + j] = cs[j];
    __syncthreads();
    if (tid < 128) {
        float ssum = 0.0f;
        #pragma unroll
        for (int t = 0; t < 16; t++) ssum += red[t][tid];
        int jg = j0 + tid;
        if (jg < HWn) atomicAdd(&g_cs[bh * HWn + jg], ssum);
    }
}

// ================= fold 1/colsum into V ====================================
__global__ void k_vnorm() {
    int idx = blockIdx.x * blockDim.x + threadIdx.x;
    if (idx >= BHT * HWn * DKn) return;
    int d = idx & 63;
    int j = (idx >> 6) % HWn;
    int bh = idx / (HWn * DKn);
    int b = bh >> 3, h = bh & 7;
    float v = g_kv[((size_t)b * HWn + j) * NKVn + h * 128 + 64 + d];
    g_vn[idx] = v / g_cs[bh * HWn + j];
}

// ================= AV: per (bh), [448,448]@[448,64] ========================
// Tile 128x64, BK=16, micro 8x4 with FFMA2 paired over m (A pairs natural).
__global__ __launch_bounds__(256, 2) void k_av() {
    int bh = blockIdx.z, b = bh >> 3, h = bh & 7;
    int i0 = blockIdx.y * 128;
    __shared__ float As[16][132];   // [j][i]
    __shared__ float Bs[16][64];    // [j][d]
    int tid = threadIdx.x, tx = tid & 15, ty = tid >> 4;
    ull acc[4][4] = {};   // [m_pair][n]
    for (int k0 = 0; k0 < HWn; k0 += 16) {
        #pragma unroll
        for (int it = 0; it < 2; it++) {
            int f = it * 256 + tid;   // 0..511
            int ii = f >> 2, j4 = f & 3;
            int ic = min(i0 + ii, HWn - 1);
            float4 e = *(const float4*)&g_E[((size_t)bh * HWn + ic) * HWn + k0 + j4 * 4];
            As[j4*4+0][ii] = e.x; As[j4*4+1][ii] = e.y; As[j4*4+2][ii] = e.z; As[j4*4+3][ii] = e.w;
        }
        {
            int row = tid >> 4, d4 = tid & 15;
            *(float4*)&Bs[row][d4 * 4] =
                *(const float4*)&g_vn[((size_t)bh * HWn + k0 + row) * DKn + d4 * 4];
        }
        __syncthreads();
        #pragma unroll
        for (int kk = 0; kk < 16; kk++) {
            const ull* ap = (const ull*)&As[kk][ty * 8];
            ull a2[4] = {ap[0], ap[1], ap[2], ap[3]};
            float4 bv = *(float4*)&Bs[kk][tx * 4];
            ull b2[4] = {pk2(bv.x,bv.x), pk2(bv.y,bv.y), pk2(bv.z,bv.z), pk2(bv.w,bv.w)};
            #pragma unroll
            for (int m2 = 0; m2 < 4; m2++)
                #pragma unroll
                for (int n = 0; n < 4; n++) fma2(acc[m2][n], a2[m2], b2[n]);
        }
        __syncthreads();
    }
    #pragma unroll
    for (int m2 = 0; m2 < 4; m2++) {
        float2 f0 = up2(acc[m2][0]), f1 = up2(acc[m2][1]);
        float2 f2 = up2(acc[m2][2]), f3 = up2(acc[m2][3]);
        int ia = i0 + ty * 8 + 2 * m2;
        if (ia < HWn)
            *(float4*)&g_res[((size_t)b * HWn + ia) * Cn + h * 64 + tx * 4] =
                make_float4(f0.x, f1.x, f2.x, f3.x);
        if (ia + 1 < HWn)
            *(float4*)&g_res[((size_t)b * HWn + ia + 1) * Cn + h * 64 + tx * 4] =
                make_float4(f0.y, f1.y, f2.y, f3.y);
    }
}

// ================= O projection + bias + residual (transposed store) =======
// out[b,c,j] = sum_n res[b,j,n]*Wo[n,c] + bo[c] + x[b,c,j]. 128x128, micro 8x8.
__global__ __launch_bounds__(256, 2) void k_out(const float* __restrict__ x,
                                                const float* __restrict__ Wo,
                                                const float* __restrict__ bo,
                                                float* __restrict__ out) {
    int b = blockIdx.z, c0 = blockIdx.y * 128, j0 = blockIdx.x * 128;
    __shared__ float As[16][128];   // [n][c]
    __shared__ float Bs[16][132];   // [n][j]
    int tid = threadIdx.x, tx = tid & 15, ty = tid >> 4;
    ull acc[8][4] = {};
    for (int k0 = 0; k0 < Cn; k0 += 16) {
        #pragma unroll
        for (int it = 0; it < 2; it++) {
            int f = it * 256 + tid;
            int row = f >> 5, c4 = f & 31;
            *(float4*)&As[row][c4 * 4] =
                *(const float4*)&Wo[(size_t)(k0 + row) * Cn + c0 + c4 * 4];
        }
        #pragma unroll
        for (int it = 0; it < 2; it++) {
            int f = it * 256 + tid;
            int jj = f >> 2, n4 = f & 3;
            int jc = min(j0 + jj, HWn - 1);
            float4 r = *(const float4*)&g_res[((size_t)b * HWn + jc) * Cn + k0 + n4 * 4];
            Bs[n4*4+0][jj] = r.x; Bs[n4*4+1][jj] = r.y; Bs[n4*4+2][jj] = r.z; Bs[n4*4+3][jj] = r.w;
        }
        __syncthreads();
        #pragma unroll
        for (int kk = 0; kk < 16; kk++) {
            float4 a0 = *(float4*)&As[kk][ty * 8];
            float4 a1 = *(float4*)&As[kk][ty * 8 + 4];
            ull a2[8] = {pk2(a0.x,a0.x), pk2(a0.y,a0.y), pk2(a0.z,a0.z), pk2(a0.w,a0.w),
                         pk2(a1.x,a1.x), pk2(a1.y,a1.y), pk2(a1.z,a1.z), pk2(a1.w,a1.w)};
            const ull* bp = (const ull*)&Bs[kk][tx * 8];
            ull b2[4] = {bp[0], bp[1], bp[2], bp[3]};
            #pragma unroll
            for (int i = 0; i < 8; i++)
                #pragma unroll
                for (int j = 0; j < 4; j++) fma2(acc[i][j], a2[i], b2[j]);
        }
        __syncthreads();
    }
    int basej = j0 + tx * 8;
    #pragma unroll
    for (int i = 0; i < 8; i++) {
        int c = c0 + ty * 8 + i;
        float bias = bo[c];
        size_t base = ((size_t)b * Cn + c) * HWn + basej;
        float ov[8];
        #pragma unroll
        for (int j2 = 0; j2 < 4; j2++) {
            float2 f = up2(acc[i][j2]);
            ov[2*j2] = f.x; ov[2*j2+1] = f.y;
        }
        if (basej + 7 < HWn) {
            float4 x0 = *(const float4*)&x[base];
            float4 x1 = *(const float4*)&x[base + 4];
            *(float4*)&out[base]     = make_float4(ov[0]+bias+x0.x, ov[1]+bias+x0.y,
                                                   ov[2]+bias+x0.z, ov[3]+bias+x0.w);
            *(float4*)&out[base + 4] = make_float4(ov[4]+bias+x1.x, ov[5]+bias+x1.y,
                                                   ov[6]+bias+x1.z, ov[7]+bias+x1.w);
        } else {
            #pragma unroll
            for (int j = 0; j < 8; j++)
                if (basej + j < HWn) out[base + j] = ov[j] + bias + x[base + j];
        }
    }
}

// ================= launch ==================================================
extern "C" void kernel_launch(void* const* d_in, const int* in_sizes, int n_in,
                              void* d_out, int out_size) {
    const float *x = 0, *s = 0, *Wkv = 0, *bkv = 0, *Wq = 0, *bq = 0, *Wo = 0, *bo = 0;
    for (int i = 0; i < n_in; i++) {
        const float* p = (const float*)d_in[i];
        switch (in_sizes[i]) {
            case 32 * 512 * 448: x = p; break;
            case 32 * 512:       s = p; break;
            case 512 * 1024:     Wkv = p; break;
            case 1024:           bkv = p; break;
            case 512 * 229376:   Wq = p; break;
            case 229376:         bq = p; break;
            case 512 * 512:      Wo = p; break;
            case 512:            bo = p; break;
        }
    }
    float* out = (float*)d_out;

    k_kv  <<<dim3(8, 4, Bn), 256>>>(x, Wkv, bkv);
    k_q   <<<NQn / 512, 256>>>(s, Wq, bq);
    k_zero<<<(BHT * HWn + 255) / 256, 256>>>();
    k_attE<<<dim3(4, 4, BHT), 256>>>();
    k_vnorm<<<(BHT * HWn * DKn + 255) / 256, 256>>>();
    k_av  <<<dim3(1, 4, BHT), 256>>>();
    k_out <<<dim3(4, 4, Bn), 256>>>(x, Wo, bo, out);
}

// round 4
// speedup vs baseline: 2.5607x; 2.2883x over previous
#include <cuda_runtime.h>
#include <cuda_bf16.h>
#include <cstdint>

#define Bn   32
#define Cn   512
#define HWn  448
#define NHn  8
#define DKn  64
#define NKVn 1024
#define NQn  (HWn * NHn * DKn)   // 229376
#define BHT  (Bn * NHn)          // 256
#define SCALE 0.125f

typedef unsigned long long ull;

// ----------------------------- fp32x2 helpers (k_out) ----------------------
__device__ __forceinline__ ull pk2(float lo, float hi) {
    ull r; asm("mov.b64 %0, {%1,%2};" : "=l"(r) : "f"(lo), "f"(hi)); return r;
}
__device__ __forceinline__ void fma2(ull& d, ull a, ull b) {
    asm("fma.rn.f32x2 %0, %1, %2, %0;" : "+l"(d) : "l"(a), "l"(b));
}
__device__ __forceinline__ float2 up2(ull v) {
    float2 r; asm("mov.b64 {%0,%1}, %2;" : "=f"(r.x), "=f"(r.y) : "l"(v)); return r;
}

// ----------------------------- mma helpers ---------------------------------
__device__ __forceinline__ uint32_t smem_u32(const void* p) {
    uint32_t a;
    asm("{ .reg .u64 t; cvta.to.shared.u64 t, %1; cvt.u32.u64 %0, t; }" : "=r"(a) : "l"(p));
    return a;
}
__device__ __forceinline__ void ldsm4(uint32_t* r, uint32_t addr) {
    asm volatile("ldmatrix.sync.aligned.m8n8.x4.shared.b16 {%0,%1,%2,%3}, [%4];"
        : "=r"(r[0]), "=r"(r[1]), "=r"(r[2]), "=r"(r[3]) : "r"(addr));
}
__device__ __forceinline__ void ldsm4t(uint32_t* r, uint32_t addr) {
    asm volatile("ldmatrix.sync.aligned.m8n8.x4.trans.shared.b16 {%0,%1,%2,%3}, [%4];"
        : "=r"(r[0]), "=r"(r[1]), "=r"(r[2]), "=r"(r[3]) : "r"(addr));
}
__device__ __forceinline__ void mma_bf16(float* c, const uint32_t* a, uint32_t b0, uint32_t b1) {
    asm volatile("mma.sync.aligned.m16n8k16.row.col.f32.bf16.bf16.f32 "
        "{%0,%1,%2,%3}, {%4,%5,%6,%7}, {%8,%9}, {%0,%1,%2,%3};"
        : "+f"(c[0]), "+f"(c[1]), "+f"(c[2]), "+f"(c[3])
        : "r"(a[0]), "r"(a[1]), "r"(a[2]), "r"(a[3]), "r"(b0), "r"(b1));
}
__device__ __forceinline__ uint32_t bf2(float a, float b) {
    __nv_bfloat162 p = __float22bfloat162_rn(make_float2(a, b));
    return *(uint32_t*)&p;
}

// --------------------------- scratch globals -------------------------------
__device__ __nv_bfloat16 g_xt [(size_t)Bn * HWn * Cn];    // [b][j][c]
__device__ __nv_bfloat16 g_Wt [(size_t)NKVn * Cn];        // [n][c]
__device__ __nv_bfloat16 g_qb [(size_t)BHT * HWn * DKn];  // [bh][i][d]
__device__ __nv_bfloat16 g_kb [(size_t)BHT * HWn * DKn];  // [bh][j][d]
__device__ float         g_v  [(size_t)BHT * HWn * DKn];  // [bh][j][d]
__device__ __nv_bfloat16 g_Eb [(size_t)BHT * HWn * HWn];  // [bh][i][j]
__device__ float         g_cs [BHT * HWn];
__device__ __nv_bfloat16 g_vt [(size_t)BHT * DKn * HWn];  // [bh][d][j] (v/cs)
__device__ float         g_res[(size_t)Bn * HWn * Cn];    // [b][i][h*64+d]

// ===================== prep: x -> xt[b][j][c] bf16 ==========================
__global__ __launch_bounds__(256) void k_prep_x(const float* __restrict__ x) {
    __shared__ float t[64][65];
    int b = blockIdx.z, j0 = blockIdx.y * 64, c0 = blockIdx.x * 64;
    int tid = threadIdx.x;
    for (int u = tid; u < 4096; u += 256) {
        int cc = u >> 6, jj = u & 63;
        t[cc][jj] = x[((size_t)b * Cn + c0 + cc) * HWn + j0 + jj];
    }
    __syncthreads();
    for (int u = tid; u < 4096; u += 256) {
        int jj = u >> 6, cc = u & 63;
        g_xt[((size_t)b * HWn + j0 + jj) * Cn + c0 + cc] = __float2bfloat16(t[cc][jj]);
    }
}

// ===================== prep: W_kv -> Wt[n][c] bf16 ==========================
__global__ __launch_bounds__(256) void k_prep_w(const float* __restrict__ Wkv) {
    __shared__ float t[64][65];
    int n0 = blockIdx.y * 64, c0 = blockIdx.x * 64;
    int tid = threadIdx.x;
    for (int u = tid; u < 4096; u += 256) {
        int cc = u >> 6, nn = u & 63;
        t[cc][nn] = Wkv[(size_t)(c0 + cc) * NKVn + n0 + nn];
    }
    __syncthreads();
    for (int u = tid; u < 4096; u += 256) {
        int nn = u >> 6, cc = u & 63;
        g_Wt[(size_t)(n0 + nn) * Cn + c0 + cc] = __float2bfloat16(t[cc][nn]);
    }
}

// ============ KV projection (mma): one head per CTA, tile 128x128 ==========
__global__ __launch_bounds__(256) void k_kv_m(const float* __restrict__ bkv) {
    __shared__ __nv_bfloat16 As[128 * 64];   // [j][c] rows 128B
    __shared__ __nv_bfloat16 Bs[128 * 64];   // [n][c]
    int h = blockIdx.x, j0 = blockIdx.y * 128, b = blockIdx.z;
    int bh = b * NHn + h;
    int tid = threadIdx.x, lane = tid & 31, wid = tid >> 5;
    int wm = wid >> 1, wn = wid & 1;
    uint32_t aBase = smem_u32(As), bBase = smem_u32(Bs);
    float acc[2][8][4] = {};
    for (int c0 = 0; c0 < Cn; c0 += 64) {
        for (int u = tid; u < 1024; u += 256) {
            int r = u >> 3, cb = u & 7;
            int j = min(j0 + r, HWn - 1);
            *(uint4*)((char*)As + r * 128 + ((cb ^ (r & 7)) << 4)) =
                *(const uint4*)(g_xt + ((size_t)b * HWn + j) * Cn + c0 + cb * 8);
            int n = h * 128 + r;
            *(uint4*)((char*)Bs + r * 128 + ((cb ^ (r & 7)) << 4)) =
                *(const uint4*)(g_Wt + (size_t)n * Cn + c0 + cb * 8);
        }
        __syncthreads();
        #pragma unroll
        for (int kk = 0; kk < 4; kk++) {
            uint32_t af[2][4], bf[4][4];
            int cb = kk * 2 + (lane >> 4);
            #pragma unroll
            for (int mi = 0; mi < 2; mi++) {
                int row = wm * 32 + mi * 16 + (lane & 15);
                ldsm4(af[mi], aBase + row * 128 + ((cb ^ (row & 7)) << 4));
            }
            #pragma unroll
            for (int np = 0; np < 4; np++) {
                int row = wn * 64 + np * 16 + (lane & 15);
                ldsm4(bf[np], bBase + row * 128 + ((cb ^ (row & 7)) << 4));
            }
            #pragma unroll
            for (int mi = 0; mi < 2; mi++)
                #pragma unroll
                for (int ni = 0; ni < 8; ni++)
                    mma_bf16(acc[mi][ni], af[mi], bf[ni >> 1][ni & 1], bf[ni >> 1][2 + (ni & 1)]);
        }
        __syncthreads();
    }
    #pragma unroll
    for (int mi = 0; mi < 2; mi++) {
        int m0 = wm * 32 + mi * 16 + (lane >> 2);
        #pragma unroll
        for (int ni = 0; ni < 8; ni++) {
            int n = wn * 64 + ni * 8 + (lane & 3) * 2;
            float b0v = bkv[h * 128 + n], b1v = bkv[h * 128 + n + 1];
            #pragma unroll
            for (int rr = 0; rr < 2; rr++) {
                int j = j0 + m0 + rr * 8;
                if (j < HWn) {
                    float v0 = acc[mi][ni][rr * 2] + b0v;
                    float v1 = acc[mi][ni][rr * 2 + 1] + b1v;
                    if (n < 64) {
                        *(uint32_t*)(g_kb + ((size_t)bh * HWn + j) * DKn + n) = bf2(v0, v1);
                    } else {
                        *(float2*)(g_v + ((size_t)bh * HWn + j) * DKn + n - 64) = make_float2(v0, v1);
                    }
                }
            }
        }
    }
}

// ================= Q projection (mma, W_q streamed fp32->bf16) =============
__global__ __launch_bounds__(256) void k_q_m(const float* __restrict__ s,
                                             const float* __restrict__ Wq,
                                             const float* __restrict__ bq) {
    __shared__ __nv_bfloat16 Ss[32 * 512];   // [m][c] rows 1024B
    __shared__ __nv_bfloat16 Bs[32 * 256];   // [c][n] rows 512B
    int n0 = blockIdx.x * 256;
    int tid = threadIdx.x, lane = tid & 31, wid = tid >> 5;
    uint32_t sBase = smem_u32(Ss), bBase = smem_u32(Bs);
    for (int u = tid; u < 4096; u += 256) {
        int m = u >> 7, f4 = u & 127;
        float4 v = *(const float4*)(s + (size_t)m * Cn + f4 * 4);
        char* dst = (char*)Ss + m * 1024 + (((f4 >> 1) ^ (m & 7)) << 4) + (f4 & 1) * 8;
        ((uint32_t*)dst)[0] = bf2(v.x, v.y);
        ((uint32_t*)dst)[1] = bf2(v.z, v.w);
    }
    float acc[2][4][4] = {};
    for (int c0 = 0; c0 < Cn; c0 += 32) {
        __syncthreads();
        for (int u = tid; u < 2048; u += 256) {
            int row = u >> 6, f4 = u & 63;
            float4 v = *(const float4*)(Wq + (size_t)(c0 + row) * NQn + n0 + f4 * 4);
            char* dst = (char*)Bs + row * 512 + (((f4 >> 1) ^ (row & 7)) << 4) + (f4 & 1) * 8;
            ((uint32_t*)dst)[0] = bf2(v.x, v.y);
            ((uint32_t*)dst)[1] = bf2(v.z, v.w);
        }
        __syncthreads();
        #pragma unroll
        for (int kk = 0; kk < 2; kk++) {
            uint32_t af[2][4], bf[2][4];
            #pragma unroll
            for (int mi = 0; mi < 2; mi++) {
                int row = mi * 16 + (lane & 15);
                int cb = ((c0 + kk * 16) >> 3) + (lane >> 4);
                ldsm4(af[mi], sBase + row * 1024 + ((cb ^ (row & 7)) << 4));
            }
            #pragma unroll
            for (int np = 0; np < 2; np++) {
                int row = kk * 16 + (lane & 15);
                int ncol = wid * 32 + np * 16 + ((lane >> 4) << 3);
                int cb = ncol >> 3;
                ldsm4t(bf[np], bBase + row * 512 + ((cb ^ (row & 7)) << 4));
            }
            #pragma unroll
            for (int mi = 0; mi < 2; mi++)
                #pragma unroll
                for (int ni = 0; ni < 4; ni++)
                    mma_bf16(acc[mi][ni], af[mi],
                             bf[ni >> 1][(ni & 1) * 2], bf[ni >> 1][(ni & 1) * 2 + 1]);
        }
    }
    #pragma unroll
    for (int mi = 0; mi < 2; mi++) {
        int m0 = mi * 16 + (lane >> 2);
        #pragma unroll
        for (int ni = 0; ni < 4; ni++) {
            int n = n0 + wid * 32 + ni * 8 + (lane & 3) * 2;
            int i = n >> 9, h = (n >> 6) & 7, d = n & 63;
            float b0v = bq[n], b1v = bq[n + 1];
            #pragma unroll
            for (int rr = 0; rr < 2; rr++) {
                int bidx = m0 + rr * 8;
                *(uint32_t*)(g_qb + (((size_t)bidx * NHn + h) * HWn + i) * DKn + d) =
                    bf2(acc[mi][ni][rr * 2] + b0v, acc[mi][ni][rr * 2 + 1] + b1v);
            }
        }
    }
}

// ================= zero colsum =============================================
__global__ void k_zero() {
    int i = blockIdx.x * blockDim.x + threadIdx.x;
    if (i < BHT * HWn) g_cs[i] = 0.0f;
}

// ======== E = exp(scale*QK^T) (mma) + column sums ==========================
// CTA: 128 i x 112 j, K=64.
__global__ __launch_bounds__(256) void k_attE_m() {
    __shared__ __nv_bfloat16 Qs[128 * 64];   // [i][d]
    __shared__ __nv_bfloat16 Ks[128 * 64];   // [j][d] (rows >=112 unused)
    int j0 = blockIdx.x * 112, i0 = blockIdx.y * 128, bh = blockIdx.z;
    int tid = threadIdx.x, lane = tid & 31, wid = tid >> 5;
    int wm = wid >> 1, wn = wid & 1;
    uint32_t qBase = smem_u32(Qs), kBase = smem_u32(Ks);
    for (int u = tid; u < 2048; u += 256) {
        int half = u >> 10, w = u & 1023, r = w >> 3, cb = w & 7;
        if (half == 0) {
            int i = min(i0 + r, HWn - 1);
            *(uint4*)((char*)Qs + r * 128 + ((cb ^ (r & 7)) << 4)) =
                *(const uint4*)(g_qb + ((size_t)bh * HWn + i) * DKn + cb * 8);
        } else {
            int j = min(j0 + r, HWn - 1);
            *(uint4*)((char*)Ks + r * 128 + ((cb ^ (r & 7)) << 4)) =
                *(const uint4*)(g_kb + ((size_t)bh * HWn + j) * DKn + cb * 8);
        }
    }
    __syncthreads();
    float acc[2][7][4] = {};
    #pragma unroll
    for (int kk = 0; kk < 4; kk++) {
        uint32_t af[2][4], bf[4][4];
        int cb = kk * 2 + (lane >> 4);
        #pragma unroll
        for (int mi = 0; mi < 2; mi++) {
            int row = wm * 32 + mi * 16 + (lane & 15);
            ldsm4(af[mi], qBase + row * 128 + ((cb ^ (row & 7)) << 4));
        }
        #pragma unroll
        for (int np = 0; np < 4; np++) {
            int row = wn * 56 + np * 16 + (lane & 15);
            ldsm4(bf[np], kBase + row * 128 + ((cb ^ (row & 7)) << 4));
        }
        #pragma unroll
        for (int mi = 0; mi < 2; mi++)
            #pragma unroll
            for (int ni = 0; ni < 7; ni++)
                mma_bf16(acc[mi][ni], af[mi], bf[ni >> 1][ni & 1], bf[ni >> 1][2 + (ni & 1)]);
    }
    #pragma unroll
    for (int ni = 0; ni < 7; ni++) {
        int n = j0 + wn * 56 + ni * 8 + (lane & 3) * 2;
        float cs0 = 0.f, cs1 = 0.f;
        #pragma unroll
        for (int mi = 0; mi < 2; mi++) {
            int ib = i0 + wm * 32 + mi * 16 + (lane >> 2);
            #pragma unroll
            for (int rr = 0; rr < 2; rr++) {
                int i = ib + rr * 8;
                float e0 = 0.f, e1 = 0.f;
                if (i < HWn) {
                    e0 = __expf(acc[mi][ni][rr * 2] * SCALE);
                    e1 = __expf(acc[mi][ni][rr * 2 + 1] * SCALE);
                    *(uint32_t*)(g_Eb + ((size_t)bh * HWn + i) * HWn + n) = bf2(e0, e1);
                }
                cs0 += e0; cs1 += e1;
            }
        }
        #pragma unroll
        for (int o = 4; o <= 16; o <<= 1) {
            cs0 += __shfl_xor_sync(0xffffffffu, cs0, o);
            cs1 += __shfl_xor_sync(0xffffffffu, cs1, o);
        }
        if ((lane >> 2) == 0) {
            atomicAdd(&g_cs[bh * HWn + n], cs0);
            atomicAdd(&g_cs[bh * HWn + n + 1], cs1);
        }
    }
}

// ========== v' = v/colsum, transposed [bh][d][j] bf16 ======================
__global__ __launch_bounds__(256) void k_vnorm_t() {
    __shared__ float t[64][65];
    int j0 = blockIdx.x * 64, bh = blockIdx.y;
    int tid = threadIdx.x;
    for (int u = tid; u < 4096; u += 256) {
        int jj = u >> 6, dd = u & 63;
        t[jj][dd] = g_v[((size_t)bh * HWn + j0 + jj) * DKn + dd] / g_cs[bh * HWn + j0 + jj];
    }
    __syncthreads();
    for (int u = tid; u < 4096; u += 256) {
        int dd = u >> 6, jj = u & 63;
        g_vt[((size_t)bh * DKn + dd) * HWn + j0 + jj] = __float2bfloat16(t[jj][dd]);
    }
}

// ========== AV (mma): res[i][d] = sum_j E * v' =============================
__global__ __launch_bounds__(256) void k_av_m() {
    __shared__ __nv_bfloat16 Es[128 * 64];  // [i][j]
    __shared__ __nv_bfloat16 Vs[64 * 64];   // [d][j]
    int i0 = blockIdx.x * 128, bh = blockIdx.y;
    int b = bh >> 3, h = bh & 7;
    int tid = threadIdx.x, lane = tid & 31, wid = tid >> 5;
    int wm = wid >> 1, wn = wid & 1;
    uint32_t eBase = smem_u32(Es), vBase = smem_u32(Vs);
    float acc[2][4][4] = {};
    for (int jc = 0; jc < HWn; jc += 64) {
        for (int u = tid; u < 1536; u += 256) {
            if (u < 1024) {
                int r = u >> 3, cb = u & 7;
                int i = min(i0 + r, HWn - 1);
                *(uint4*)((char*)Es + r * 128 + ((cb ^ (r & 7)) << 4)) =
                    *(const uint4*)(g_Eb + ((size_t)bh * HWn + i) * HWn + jc + cb * 8);
            } else {
                int w = u - 1024, r = w >> 3, cb = w & 7;
                *(uint4*)((char*)Vs + r * 128 + ((cb ^ (r & 7)) << 4)) =
                    *(const uint4*)(g_vt + ((size_t)bh * DKn + r) * HWn + jc + cb * 8);
            }
        }
        __syncthreads();
        #pragma unroll
        for (int kk = 0; kk < 4; kk++) {
            uint32_t af[2][4], bf[2][4];
            int cb = kk * 2 + (lane >> 4);
            #pragma unroll
            for (int mi = 0; mi < 2; mi++) {
                int row = wm * 32 + mi * 16 + (lane & 15);
                ldsm4(af[mi], eBase + row * 128 + ((cb ^ (row & 7)) << 4));
            }
            #pragma unroll
            for (int np = 0; np < 2; np++) {
                int row = wn * 32 + np * 16 + (lane & 15);
                ldsm4(bf[np], vBase + row * 128 + ((cb ^ (row & 7)) << 4));
            }
            #pragma unroll
            for (int mi = 0; mi < 2; mi++)
                #pragma unroll
                for (int ni = 0; ni < 4; ni++)
                    mma_bf16(acc[mi][ni], af[mi], bf[ni >> 1][ni & 1], bf[ni >> 1][2 + (ni & 1)]);
        }
        __syncthreads();
    }
    #pragma unroll
    for (int mi = 0; mi < 2; mi++) {
        int ib = i0 + wm * 32 + mi * 16 + (lane >> 2);
        #pragma unroll
        for (int ni = 0; ni < 4; ni++) {
            int d = wn * 32 + ni * 8 + (lane & 3) * 2;
            #pragma unroll
            for (int rr = 0; rr < 2; rr++) {
                int i = ib + rr * 8;
                if (i < HWn)
                    *(float2*)(g_res + ((size_t)b * HWn + i) * Cn + h * 64 + d) =
                        make_float2(acc[mi][ni][rr * 2], acc[mi][ni][rr * 2 + 1]);
            }
        }
    }
}

// ================= O projection + bias + residual (fp32 FFMA2) =============
__global__ __launch_bounds__(256, 2) void k_out(const float* __restrict__ x,
                                                const float* __restrict__ Wo,
                                                const float* __restrict__ bo,
                                                float* __restrict__ out) {
    int b = blockIdx.z, c0 = blockIdx.y * 128, j0 = blockIdx.x * 128;
    __shared__ float As[16][128];
    __shared__ float Bs[16][132];
    int tid = threadIdx.x, tx = tid & 15, ty = tid >> 4;
    ull acc[8][4] = {};
    for (int k0 = 0; k0 < Cn; k0 += 16) {
        #pragma unroll
        for (int it = 0; it < 2; it++) {
            int f = it * 256 + tid;
            int row = f >> 5, c4 = f & 31;
            *(float4*)&As[row][c4 * 4] =
                *(const float4*)&Wo[(size_t)(k0 + row) * Cn + c0 + c4 * 4];
        }
        #pragma unroll
        for (int it = 0; it < 2; it++) {
            int f = it * 256 + tid;
            int jj = f >> 2, n4 = f & 3;
            int jc = min(j0 + jj, HWn - 1);
            float4 r = *(const float4*)&g_res[((size_t)b * HWn + jc) * Cn + k0 + n4 * 4];
            Bs[n4*4+0][jj] = r.x; Bs[n4*4+1][jj] = r.y; Bs[n4*4+2][jj] = r.z; Bs[n4*4+3][jj] = r.w;
        }
        __syncthreads();
        #pragma unroll
        for (int kk = 0; kk < 16; kk++) {
            float4 a0 = *(float4*)&As[kk][ty * 8];
            float4 a1 = *(float4*)&As[kk][ty * 8 + 4];
            ull a2[8] = {pk2(a0.x,a0.x), pk2(a0.y,a0.y), pk2(a0.z,a0.z), pk2(a0.w,a0.w),
                         pk2(a1.x,a1.x), pk2(a1.y,a1.y), pk2(a1.z,a1.z), pk2(a1.w,a1.w)};
            const ull* bp = (const ull*)&Bs[kk][tx * 8];
            ull b2[4] = {bp[0], bp[1], bp[2], bp[3]};
            #pragma unroll
            for (int i = 0; i < 8; i++)
                #pragma unroll
                for (int j = 0; j < 4; j++) fma2(acc[i][j], a2[i], b2[j]);
        }
        __syncthreads();
    }
    int basej = j0 + tx * 8;
    #pragma unroll
    for (int i = 0; i < 8; i++) {
        int c = c0 + ty * 8 + i;
        float bias = bo[c];
        size_t base = ((size_t)b * Cn + c) * HWn + basej;
        float ov[8];
        #pragma unroll
        for (int j2 = 0; j2 < 4; j2++) {
            float2 f = up2(acc[i][j2]);
            ov[2*j2] = f.x; ov[2*j2+1] = f.y;
        }
        if (basej + 7 < HWn) {
            float4 x0 = *(const float4*)&x[base];
            float4 x1 = *(const float4*)&x[base + 4];
            *(float4*)&out[base]     = make_float4(ov[0]+bias+x0.x, ov[1]+bias+x0.y,
                                                   ov[2]+bias+x0.z, ov[3]+bias+x0.w);
            *(float4*)&out[base + 4] = make_float4(ov[4]+bias+x1.x, ov[5]+bias+x1.y,
                                                   ov[6]+bias+x1.z, ov[7]+bias+x1.w);
        } else {
            #pragma unroll
            for (int j = 0; j < 8; j++)
                if (basej + j < HWn) out[base + j] = ov[j] + bias + x[base + j];
        }
    }
}

// ================= launch ==================================================
extern "C" void kernel_launch(void* const* d_in, const int* in_sizes, int n_in,
                              void* d_out, int out_size) {
    const float *x = 0, *s = 0, *Wkv = 0, *bkv = 0, *Wq = 0, *bq = 0, *Wo = 0, *bo = 0;
    for (int i = 0; i < n_in; i++) {
        const float* p = (const float*)d_in[i];
        switch (in_sizes[i]) {
            case 32 * 512 * 448: x = p; break;
            case 32 * 512:       s = p; break;
            case 512 * 1024:     Wkv = p; break;
            case 1024:           bkv = p; break;
            case 512 * 229376:   Wq = p; break;
            case 229376:         bq = p; break;
            case 512 * 512:      Wo = p; break;
            case 512:            bo = p; break;
        }
    }
    float* out = (float*)d_out;

    k_prep_x <<<dim3(8, 7, Bn), 256>>>(x);
    k_prep_w <<<dim3(8, 16), 256>>>(Wkv);
    k_q_m    <<<NQn / 256, 256>>>(s, Wq, bq);
    k_kv_m   <<<dim3(NHn, 4, Bn), 256>>>(bkv);
    k_zero   <<<(BHT * HWn + 255) / 256, 256>>>();
    k_attE_m <<<dim3(4, 4, BHT), 256>>>();
    k_vnorm_t<<<dim3(7, BHT), 256>>>();
    k_av_m   <<<dim3(4, BHT), 256>>>();
    k_out    <<<dim3(4, 4, Bn), 256>>>(x, Wo, bo, out);
}

// round 6
// speedup vs baseline: 4.1465x; 1.6192x over previous
#include <cuda_runtime.h>
#include <cuda_bf16.h>
#include <cstdint>

#define Bn   32
#define Cn   512
#define HWn  448
#define NHn  8
#define DKn  64
#define NKVn 1024
#define NQn  (HWn * NHn * DKn)   // 229376
#define BHT  (Bn * NHn)          // 256
#define SCALE 0.125f

typedef unsigned long long ull;

// ----------------------------- mma / async helpers -------------------------
__device__ __forceinline__ uint32_t smem_u32(const void* p) {
    uint32_t a;
    asm("{ .reg .u64 t; cvta.to.shared.u64 t, %1; cvt.u32.u64 %0, t; }" : "=r"(a) : "l"(p));
    return a;
}
__device__ __forceinline__ void ldsm4(uint32_t* r, uint32_t addr) {
    asm volatile("ldmatrix.sync.aligned.m8n8.x4.shared.b16 {%0,%1,%2,%3}, [%4];"
        : "=r"(r[0]), "=r"(r[1]), "=r"(r[2]), "=r"(r[3]) : "r"(addr));
}
__device__ __forceinline__ void ldsm4t(uint32_t* r, uint32_t addr) {
    asm volatile("ldmatrix.sync.aligned.m8n8.x4.trans.shared.b16 {%0,%1,%2,%3}, [%4];"
        : "=r"(r[0]), "=r"(r[1]), "=r"(r[2]), "=r"(r[3]) : "r"(addr));
}
__device__ __forceinline__ void mma_bf16(float* c, const uint32_t* a, uint32_t b0, uint32_t b1) {
    asm volatile("mma.sync.aligned.m16n8k16.row.col.f32.bf16.bf16.f32 "
        "{%0,%1,%2,%3}, {%4,%5,%6,%7}, {%8,%9}, {%0,%1,%2,%3};"
        : "+f"(c[0]), "+f"(c[1]), "+f"(c[2]), "+f"(c[3])
        : "r"(a[0]), "r"(a[1]), "r"(a[2]), "r"(a[3]), "r"(b0), "r"(b1));
}
__device__ __forceinline__ uint32_t bf2(float a, float b) {
    __nv_bfloat162 p = __float22bfloat162_rn(make_float2(a, b));
    return *(uint32_t*)&p;
}
__device__ __forceinline__ void cpa16(uint32_t dst, const void* src) {
    asm volatile("cp.async.cg.shared.global [%0], [%1], 16;" :: "r"(dst), "l"(src));
}
#define CP_COMMIT() asm volatile("cp.async.commit_group;" ::: "memory")
#define CP_WAIT1()  asm volatile("cp.async.wait_group 1;" ::: "memory")
#define CP_WAIT0()  asm volatile("cp.async.wait_group 0;" ::: "memory")

// --------------------------- scratch globals -------------------------------
__device__ __nv_bfloat16 g_xt  [(size_t)Bn * HWn * Cn];    // [b][j][c]
__device__ __nv_bfloat16 g_Wt  [(size_t)NKVn * Cn];        // [n][c]
__device__ __nv_bfloat16 g_WoT [(size_t)Cn * Cn];          // [c][n]
__device__ __nv_bfloat16 g_qb  [(size_t)BHT * HWn * DKn];  // [bh][i][d]
__device__ __nv_bfloat16 g_kb  [(size_t)BHT * HWn * DKn];  // [bh][j][d]
__device__ float         g_v   [(size_t)BHT * HWn * DKn];  // [bh][j][d]
__device__ __nv_bfloat16 g_Eb  [(size_t)BHT * HWn * HWn];  // [bh][i][j]
__device__ float         g_cs  [BHT * HWn];
__device__ __nv_bfloat16 g_vt  [(size_t)BHT * DKn * HWn];  // [bh][d][j] (v/cs)
__device__ __nv_bfloat16 g_resb[(size_t)Bn * HWn * Cn];    // [b][i][h*64+d] bf16

// ===================== prep: x -> xt[b][j][c] bf16 ==========================
__global__ __launch_bounds__(256) void k_prep_x(const float* __restrict__ x) {
    __shared__ float t[64][65];
    int b = blockIdx.z, j0 = blockIdx.y * 64, c0 = blockIdx.x * 64;
    int tid = threadIdx.x;
    for (int u = tid; u < 4096; u += 256) {
        int cc = u >> 6, jj = u & 63;
        t[cc][jj] = x[((size_t)b * Cn + c0 + cc) * HWn + j0 + jj];
    }
    __syncthreads();
    for (int u = tid; u < 4096; u += 256) {
        int jj = u >> 6, cc = u & 63;
        g_xt[((size_t)b * HWn + j0 + jj) * Cn + c0 + cc] = __float2bfloat16(t[cc][jj]);
    }
}

// ===================== prep: W_kv -> Wt[n][c] bf16 ==========================
__global__ __launch_bounds__(256) void k_prep_w(const float* __restrict__ Wkv) {
    __shared__ float t[64][65];
    int n0 = blockIdx.y * 64, c0 = blockIdx.x * 64;
    int tid = threadIdx.x;
    for (int u = tid; u < 4096; u += 256) {
        int cc = u >> 6, nn = u & 63;
        t[cc][nn] = Wkv[(size_t)(c0 + cc) * NKVn + n0 + nn];
    }
    __syncthreads();
    for (int u = tid; u < 4096; u += 256) {
        int nn = u >> 6, cc = u & 63;
        g_Wt[(size_t)(n0 + nn) * Cn + c0 + cc] = __float2bfloat16(t[cc][nn]);
    }
}

// ===================== prep: W_o -> WoT[c][n] bf16 ==========================
__global__ __launch_bounds__(256) void k_prep_wo(const float* __restrict__ Wo) {
    __shared__ float t[64][65];
    int c0 = blockIdx.y * 64, n0 = blockIdx.x * 64;
    int tid = threadIdx.x;
    for (int u = tid; u < 4096; u += 256) {
        int nn = u >> 6, cc = u & 63;
        t[nn][cc] = Wo[(size_t)(n0 + nn) * Cn + c0 + cc];
    }
    __syncthreads();
    for (int u = tid; u < 4096; u += 256) {
        int cc = u >> 6, nn = u & 63;
        g_WoT[(size_t)(c0 + cc) * Cn + n0 + nn] = __float2bfloat16(t[nn][cc]);
    }
}

// ============ KV projection (mma, cp.async 2-stage): head per CTA ==========
__global__ __launch_bounds__(256) void k_kv_m(const float* __restrict__ bkv) {
    extern __shared__ char sm[];
    int h = blockIdx.x, j0 = blockIdx.y * 128, b = blockIdx.z;
    int bh = b * NHn + h;
    int tid = threadIdx.x, lane = tid & 31, wid = tid >> 5;
    int wm = wid >> 1, wn = wid & 1;
    uint32_t base = smem_u32(sm);
    float acc[2][8][4] = {};
    auto issue = [&](int st, int c0) {
        uint32_t ab = base + st * 32768, bb = ab + 16384;
        for (int u = tid; u < 1024; u += 256) {
            int r = u >> 3, cb = u & 7;
            int j = min(j0 + r, HWn - 1);
            cpa16(ab + r * 128 + ((cb ^ (r & 7)) << 4),
                  g_xt + ((size_t)b * HWn + j) * Cn + c0 + cb * 8);
            cpa16(bb + r * 128 + ((cb ^ (r & 7)) << 4),
                  g_Wt + (size_t)(h * 128 + r) * Cn + c0 + cb * 8);
        }
        CP_COMMIT();
    };
    issue(0, 0);
    for (int s = 0; s < 8; s++) {
        int st = s & 1;
        if (s < 7) { issue(st ^ 1, (s + 1) * 64); CP_WAIT1(); } else { CP_WAIT0(); }
        __syncthreads();
        uint32_t aBase = base + st * 32768, bBase = aBase + 16384;
        #pragma unroll
        for (int kk = 0; kk < 4; kk++) {
            uint32_t af[2][4], bf[4][4];
            int cb = kk * 2 + (lane >> 4);
            #pragma unroll
            for (int mi = 0; mi < 2; mi++) {
                int row = wm * 32 + mi * 16 + (lane & 15);
                ldsm4(af[mi], aBase + row * 128 + ((cb ^ (row & 7)) << 4));
            }
            #pragma unroll
            for (int np = 0; np < 4; np++) {
                int row = wn * 64 + np * 16 + (lane & 15);
                ldsm4(bf[np], bBase + row * 128 + ((cb ^ (row & 7)) << 4));
            }
            #pragma unroll
            for (int mi = 0; mi < 2; mi++)
                #pragma unroll
                for (int ni = 0; ni < 8; ni++)
                    mma_bf16(acc[mi][ni], af[mi], bf[ni >> 1][ni & 1], bf[ni >> 1][2 + (ni & 1)]);
        }
        __syncthreads();
    }
    #pragma unroll
    for (int mi = 0; mi < 2; mi++) {
        int m0 = wm * 32 + mi * 16 + (lane >> 2);
        #pragma unroll
        for (int ni = 0; ni < 8; ni++) {
            int n = wn * 64 + ni * 8 + (lane & 3) * 2;
            float b0v = bkv[h * 128 + n], b1v = bkv[h * 128 + n + 1];
            #pragma unroll
            for (int rr = 0; rr < 2; rr++) {
                int j = j0 + m0 + rr * 8;
                if (j < HWn) {
                    float v0 = acc[mi][ni][rr * 2] + b0v;
                    float v1 = acc[mi][ni][rr * 2 + 1] + b1v;
                    if (n < 64) {
                        *(uint32_t*)(g_kb + ((size_t)bh * HWn + j) * DKn + n) = bf2(v0, v1);
                    } else {
                        *(float2*)(g_v + ((size_t)bh * HWn + j) * DKn + n - 64) = make_float2(v0, v1);
                    }
                }
            }
        }
    }
}

// ================= Q projection (mma, reg-prefetch pipeline) ===============
__global__ __launch_bounds__(256) void k_q_m(const float* __restrict__ s,
                                             const float* __restrict__ Wq,
                                             const float* __restrict__ bq) {
    __shared__ __nv_bfloat16 Ss[32 * 512];   // [m][c] rows 1024B
    __shared__ __nv_bfloat16 Bs[32 * 256];   // [c][n] rows 512B
    int n0 = blockIdx.x * 256;
    int tid = threadIdx.x, lane = tid & 31, wid = tid >> 5;
    uint32_t sBase = smem_u32(Ss), bBase = smem_u32(Bs);
    for (int u = tid; u < 4096; u += 256) {
        int m = u >> 7, f4 = u & 127;
        float4 v = *(const float4*)(s + (size_t)m * Cn + f4 * 4);
        char* dst = (char*)Ss + m * 1024 + (((f4 >> 1) ^ (m & 7)) << 4) + (f4 & 1) * 8;
        ((uint32_t*)dst)[0] = bf2(v.x, v.y);
        ((uint32_t*)dst)[1] = bf2(v.z, v.w);
    }
    float4 pf[8];
    #pragma unroll
    for (int it = 0; it < 8; it++) {
        int u = it * 256 + tid, row = u >> 6, f4 = u & 63;
        pf[it] = *(const float4*)(Wq + (size_t)row * NQn + n0 + f4 * 4);
    }
    float acc[2][4][4] = {};
    for (int c0 = 0; c0 < Cn; c0 += 32) {
        __syncthreads();
        #pragma unroll
        for (int it = 0; it < 8; it++) {
            int u = it * 256 + tid, row = u >> 6, f4 = u & 63;
            char* dst = (char*)Bs + row * 512 + (((f4 >> 1) ^ (row & 7)) << 4) + (f4 & 1) * 8;
            ((uint32_t*)dst)[0] = bf2(pf[it].x, pf[it].y);
            ((uint32_t*)dst)[1] = bf2(pf[it].z, pf[it].w);
        }
        __syncthreads();
        if (c0 + 32 < Cn) {
            #pragma unroll
            for (int it = 0; it < 8; it++) {
                int u = it * 256 + tid, row = u >> 6, f4 = u & 63;
                pf[it] = *(const float4*)(Wq + (size_t)(c0 + 32 + row) * NQn + n0 + f4 * 4);
            }
        }
        #pragma unroll
        for (int kk = 0; kk < 2; kk++) {
            uint32_t af[2][4], bf[2][4];
            #pragma unroll
            for (int mi = 0; mi < 2; mi++) {
                int row = mi * 16 + (lane & 15);
                int cb = ((c0 + kk * 16) >> 3) + (lane >> 4);
                ldsm4(af[mi], sBase + row * 1024 + ((cb ^ (row & 7)) << 4));
            }
            #pragma unroll
            for (int np = 0; np < 2; np++) {
                int row = kk * 16 + (lane & 15);
                int ncol = wid * 32 + np * 16 + ((lane >> 4) << 3);
                int cb = ncol >> 3;
                ldsm4t(bf[np], bBase + row * 512 + ((cb ^ (row & 7)) << 4));
            }
            #pragma unroll
            for (int mi = 0; mi < 2; mi++)
                #pragma unroll
                for (int ni = 0; ni < 4; ni++)
                    mma_bf16(acc[mi][ni], af[mi],
                             bf[ni >> 1][(ni & 1) * 2], bf[ni >> 1][(ni & 1) * 2 + 1]);
        }
    }
    #pragma unroll
    for (int mi = 0; mi < 2; mi++) {
        int m0 = mi * 16 + (lane >> 2);
        #pragma unroll
        for (int ni = 0; ni < 4; ni++) {
            int n = n0 + wid * 32 + ni * 8 + (lane & 3) * 2;
            int i = n >> 9, h = (n >> 6) & 7, d = n & 63;
            float b0v = bq[n], b1v = bq[n + 1];
            #pragma unroll
            for (int rr = 0; rr < 2; rr++) {
                int bidx = m0 + rr * 8;
                *(uint32_t*)(g_qb + (((size_t)bidx * NHn + h) * HWn + i) * DKn + d) =
                    bf2(acc[mi][ni][rr * 2] + b0v, acc[mi][ni][rr * 2 + 1] + b1v);
            }
        }
    }
}

// ================= zero colsum =============================================
__global__ void k_zero() {
    int i = blockIdx.x * blockDim.x + threadIdx.x;
    if (i < BHT * HWn) g_cs[i] = 0.0f;
}

// ======== E = exp(scale*QK^T) (mma) + column sums ==========================
__global__ __launch_bounds__(256) void k_attE_m() {
    __shared__ __nv_bfloat16 Qs[128 * 64];
    __shared__ __nv_bfloat16 Ks[128 * 64];
    int j0 = blockIdx.x * 112, i0 = blockIdx.y * 128, bh = blockIdx.z;
    int tid = threadIdx.x, lane = tid & 31, wid = tid >> 5;
    int wm = wid >> 1, wn = wid & 1;
    uint32_t qBase = smem_u32(Qs), kBase = smem_u32(Ks);
    for (int u = tid; u < 2048; u += 256) {
        int half = u >> 10, w = u & 1023, r = w >> 3, cb = w & 7;
        if (half == 0) {
            int i = min(i0 + r, HWn - 1);
            *(uint4*)((char*)Qs + r * 128 + ((cb ^ (r & 7)) << 4)) =
                *(const uint4*)(g_qb + ((size_t)bh * HWn + i) * DKn + cb * 8);
        } else {
            int j = min(j0 + r, HWn - 1);
            *(uint4*)((char*)Ks + r * 128 + ((cb ^ (r & 7)) << 4)) =
                *(const uint4*)(g_kb + ((size_t)bh * HWn + j) * DKn + cb * 8);
        }
    }
    __syncthreads();
    float acc[2][7][4] = {};
    #pragma unroll
    for (int kk = 0; kk < 4; kk++) {
        uint32_t af[2][4], bf[4][4];
        int cb = kk * 2 + (lane >> 4);
        #pragma unroll
        for (int mi = 0; mi < 2; mi++) {
            int row = wm * 32 + mi * 16 + (lane & 15);
            ldsm4(af[mi], qBase + row * 128 + ((cb ^ (row & 7)) << 4));
        }
        #pragma unroll
        for (int np = 0; np < 4; np++) {
            int row = wn * 56 + np * 16 + (lane & 15);
            ldsm4(bf[np], kBase + row * 128 + ((cb ^ (row & 7)) << 4));
        }
        #pragma unroll
        for (int mi = 0; mi < 2; mi++)
            #pragma unroll
            for (int ni = 0; ni < 7; ni++)
                mma_bf16(acc[mi][ni], af[mi], bf[ni >> 1][ni & 1], bf[ni >> 1][2 + (ni & 1)]);
    }
    #pragma unroll
    for (int ni = 0; ni < 7; ni++) {
        int n = j0 + wn * 56 + ni * 8 + (lane & 3) * 2;
        float cs0 = 0.f, cs1 = 0.f;
        #pragma unroll
        for (int mi = 0; mi < 2; mi++) {
            int ib = i0 + wm * 32 + mi * 16 + (lane >> 2);
            #pragma unroll
            for (int rr = 0; rr < 2; rr++) {
                int i = ib + rr * 8;
                float e0 = 0.f, e1 = 0.f;
                if (i < HWn) {
                    e0 = __expf(acc[mi][ni][rr * 2] * SCALE);
                    e1 = __expf(acc[mi][ni][rr * 2 + 1] * SCALE);
                    *(uint32_t*)(g_Eb + ((size_t)bh * HWn + i) * HWn + n) = bf2(e0, e1);
                }
                cs0 += e0; cs1 += e1;
            }
        }
        #pragma unroll
        for (int o = 4; o <= 16; o <<= 1) {
            cs0 += __shfl_xor_sync(0xffffffffu, cs0, o);
            cs1 += __shfl_xor_sync(0xffffffffu, cs1, o);
        }
        if ((lane >> 2) == 0) {
            atomicAdd(&g_cs[bh * HWn + n], cs0);
            atomicAdd(&g_cs[bh * HWn + n + 1], cs1);
        }
    }
}

// ========== v' = v/colsum, transposed [bh][d][j] bf16 ======================
__global__ __launch_bounds__(256) void k_vnorm_t() {
    __shared__ float t[64][65];
    int j0 = blockIdx.x * 64, bh = blockIdx.y;
    int tid = threadIdx.x;
    for (int u = tid; u < 4096; u += 256) {
        int jj = u >> 6, dd = u & 63;
        t[jj][dd] = g_v[((size_t)bh * HWn + j0 + jj) * DKn + dd] / g_cs[bh * HWn + j0 + jj];
    }
    __syncthreads();
    for (int u = tid; u < 4096; u += 256) {
        int dd = u >> 6, jj = u & 63;
        g_vt[((size_t)bh * DKn + dd) * HWn + j0 + jj] = __float2bfloat16(t[jj][dd]);
    }
}

// ========== AV (mma, cp.async 2-stage): res[i][d] = sum_j E * v' ===========
__global__ __launch_bounds__(256) void k_av_m() {
    extern __shared__ char sm[];
    int i0 = blockIdx.x * 128, bh = blockIdx.y;
    int b = bh >> 3, h = bh & 7;
    int tid = threadIdx.x, lane = tid & 31, wid = tid >> 5;
    int wm = wid >> 1, wn = wid & 1;
    uint32_t base = smem_u32(sm);
    float acc[2][4][4] = {};
    auto issue = [&](int st, int jc) {
        uint32_t eb = base + st * 24576, vb = eb + 16384;
        for (int u = tid; u < 1536; u += 256) {
            if (u < 1024) {
                int r = u >> 3, cb = u & 7;
                int i = min(i0 + r, HWn - 1);
                cpa16(eb + r * 128 + ((cb ^ (r & 7)) << 4),
                      g_Eb + ((size_t)bh * HWn + i) * HWn + jc + cb * 8);
            } else {
                int w = u - 1024, r = w >> 3, cb = w & 7;
                cpa16(vb + r * 128 + ((cb ^ (r & 7)) << 4),
                      g_vt + ((size_t)bh * DKn + r) * HWn + jc + cb * 8);
            }
        }
        CP_COMMIT();
    };
    issue(0, 0);
    for (int s = 0; s < 7; s++) {
        int st = s & 1;
        if (s < 6) { issue(st ^ 1, (s + 1) * 64); CP_WAIT1(); } else { CP_WAIT0(); }
        __syncthreads();
        uint32_t eBase = base + st * 24576, vBase = eBase + 16384;
        #pragma unroll
        for (int kk = 0; kk < 4; kk++) {
            uint32_t af[2][4], bf[2][4];
            int cb = kk * 2 + (lane >> 4);
            #pragma unroll
            for (int mi = 0; mi < 2; mi++) {
                int row = wm * 32 + mi * 16 + (lane & 15);
                ldsm4(af[mi], eBase + row * 128 + ((cb ^ (row & 7)) << 4));
            }
            #pragma unroll
            for (int np = 0; np < 2; np++) {
                int row = wn * 32 + np * 16 + (lane & 15);
                ldsm4(bf[np], vBase + row * 128 + ((cb ^ (row & 7)) << 4));
            }
            #pragma unroll
            for (int mi = 0; mi < 2; mi++)
                #pragma unroll
                for (int ni = 0; ni < 4; ni++)
                    mma_bf16(acc[mi][ni], af[mi], bf[ni >> 1][ni & 1], bf[ni >> 1][2 + (ni & 1)]);
        }
        __syncthreads();
    }
    #pragma unroll
    for (int mi = 0; mi < 2; mi++) {
        int ib = i0 + wm * 32 + mi * 16 + (lane >> 2);
        #pragma unroll
        for (int ni = 0; ni < 4; ni++) {
            int d = wn * 32 + ni * 8 + (lane & 3) * 2;
            #pragma unroll
            for (int rr = 0; rr < 2; rr++) {
                int i = ib + rr * 8;
                if (i < HWn)
                    *(uint32_t*)(g_resb + ((size_t)b * HWn + i) * Cn + h * 64 + d) =
                        bf2(acc[mi][ni][rr * 2], acc[mi][ni][rr * 2 + 1]);
            }
        }
    }
}

// ====== O projection (mma bf16, cp.async 2-stage) + bias + residual ========
// out[b,c,j] = sum_n WoT[c][n]*res[j][n] + bo[c] + x[b,c,j]
__global__ __launch_bounds__(256) void k_out_m(const float* __restrict__ x,
                                               const float* __restrict__ bo,
                                               float* __restrict__ out) {
    extern __shared__ char sm[];
    int b = blockIdx.z, c0 = blockIdx.y * 128, j0 = blockIdx.x * 128;
    int tid = threadIdx.x, lane = tid & 31, wid = tid >> 5;
    int wm = wid >> 1, wn = wid & 1;
    uint32_t base = smem_u32(sm);
    float acc[2][8][4] = {};
    auto issue = [&](int st, int n0) {
        uint32_t ab = base + st * 32768, bb = ab + 16384;
        for (int u = tid; u < 1024; u += 256) {
            int r = u >> 3, cb = u & 7;
            cpa16(ab + r * 128 + ((cb ^ (r & 7)) << 4),
                  g_WoT + (size_t)(c0 + r) * Cn + n0 + cb * 8);
            int j = min(j0 + r, HWn - 1);
            cpa16(bb + r * 128 + ((cb ^ (r & 7)) << 4),
                  g_resb + ((size_t)b * HWn + j) * Cn + n0 + cb * 8);
        }
        CP_COMMIT();
    };
    issue(0, 0);
    for (int s = 0; s < 8; s++) {
        int st = s & 1;
        if (s < 7) { issue(st ^ 1, (s + 1) * 64); CP_WAIT1(); } else { CP_WAIT0(); }
        __syncthreads();
        uint32_t aBase = base + st * 32768, bBase = aBase + 16384;
        #pragma unroll
        for (int kk = 0; kk < 4; kk++) {
            uint32_t af[2][4], bf[4][4];
            int cb = kk * 2 + (lane >> 4);
            #pragma unroll
            for (int mi = 0; mi < 2; mi++) {
                int row = wm * 32 + mi * 16 + (lane & 15);
                ldsm4(af[mi], aBase + row * 128 + ((cb ^ (row & 7)) << 4));
            }
            #pragma unroll
            for (int np = 0; np < 4; np++) {
                int row = wn * 64 + np * 16 + (lane & 15);
                ldsm4(bf[np], bBase + row * 128 + ((cb ^ (row & 7)) << 4));
            }
            #pragma unroll
            for (int mi = 0; mi < 2; mi++)
                #pragma unroll
                for (int ni = 0; ni < 8; ni++)
                    mma_bf16(acc[mi][ni], af[mi], bf[ni >> 1][ni & 1], bf[ni >> 1][2 + (ni & 1)]);
        }
        __syncthreads();
    }
    // epilogue: stage fp32 tile [128 c][64 j] per half, then coalesced out
    float* stg = (float*)sm;   // 128*66*4 = 33792 B (mma reads are done)
    #pragma unroll
    for (int half = 0; half < 2; half++) {
        if (wn == half) {
            #pragma unroll
            for (int mi = 0; mi < 2; mi++) {
                #pragma unroll
                for (int ni = 0; ni < 8; ni++) {
                    int jj = ni * 8 + (lane & 3) * 2;
                    #pragma unroll
                    for (int rr = 0; rr < 2; rr++) {
                        int c = wm * 32 + mi * 16 + (lane >> 2) + rr * 8;
                        stg[c * 66 + jj]     = acc[mi][ni][rr * 2];
                        stg[c * 66 + jj + 1] = acc[mi][ni][rr * 2 + 1];
                    }
                }
            }
        }
        __syncthreads();
        for (int u = tid; u < 4096; u += 256) {
            int c = u >> 5, jj = (u & 31) * 2;
            int j = j0 + half * 64 + jj;
            if (j < HWn) {
                size_t o = ((size_t)b * Cn + c0 + c) * HWn + j;
                float bias = bo[c0 + c];
                float2 xv = *(const float2*)(x + o);
                float2 r = make_float2(stg[c * 66 + jj] + bias + xv.x,
                                       stg[c * 66 + jj + 1] + bias + xv.y);
                *(float2*)(out + o) = r;
            }
        }
        __syncthreads();
    }
}

// ================= launch ==================================================
extern "C" void kernel_launch(void* const* d_in, const int* in_sizes, int n_in,
                              void* d_out, int out_size) {
    const float *x = 0, *s = 0, *Wkv = 0, *bkv = 0, *Wq = 0, *bq = 0, *Wo = 0, *bo = 0;
    for (int i = 0; i < n_in; i++) {
        const float* p = (const float*)d_in[i];
        switch (in_sizes[i]) {
            case 32 * 512 * 448: x = p; break;
            case 32 * 512:       s = p; break;
            case 512 * 1024:     Wkv = p; break;
            case 1024:           bkv = p; break;
            case 512 * 229376:   Wq = p; break;
            case 229376:         bq = p; break;
            case 512 * 512:      Wo = p; break;
            case 512:            bo = p; break;
        }
    }
    float* out = (float*)d_out;

    static int init = 0;
    if (!init) {
        cudaFuncSetAttribute(k_kv_m,  cudaFuncAttributeMaxDynamicSharedMemorySize, 65536);
        cudaFuncSetAttribute(k_av_m,  cudaFuncAttributeMaxDynamicSharedMemorySize, 49152);
        cudaFuncSetAttribute(k_out_m, cudaFuncAttributeMaxDynamicSharedMemorySize, 65536);
        init = 1;
    }

    k_prep_x <<<dim3(8, 7, Bn), 256>>>(x);
    k_prep_w <<<dim3(8, 16), 256>>>(Wkv);
    k_prep_wo<<<dim3(8, 8), 256>>>(Wo);
    k_q_m    <<<NQn / 256, 256>>>(s, Wq, bq);
    k_kv_m   <<<dim3(NHn, 4, Bn), 256, 65536>>>(bkv);
    k_zero   <<<(BHT * HWn + 255) / 256, 256>>>();
    k_attE_m <<<dim3(4, 4, BHT), 256>>>();
    k_vnorm_t<<<dim3(7, BHT), 256>>>();
    k_av_m   <<<dim3(4, BHT), 256, 49152>>>();
    k_out_m  <<<dim3(4, 4, Bn), 256, 65536>>>(x, bo, out);
}